// round 11
// baseline (speedup 1.0000x reference)
#include <cuda_runtime.h>
#include <math.h>

#define HW      131072      // 256*512
#define W_IMG   512
#define H_IMG   256
#define NC      256
#define NB      2
#define NOUT    16          // 13 pos + 1 reg + 2 off

typedef unsigned long long ull;

// Scratch for evident = relu(pos conv): [2,13,H,W]
__device__ float g_ev[NB * 13 * HW];

// ---------------- compile-time Hough region geometry ----------------
__host__ __device__ constexpr int region_of(int ys, int xs) {
    int r2 = ys * ys + xs * xs;
    if (r2 <= 4) return 0;
    int ring = (r2 <= 64) ? 0 : (r2 <= 256) ? 1 : 2;
    int bin = 0;
    if (ys > 0)      bin = (xs > 0) ? 0 : 1;
    else if (ys < 0) bin = (xs < 0) ? 2 : 3;
    else             bin = (xs > 0) ? 0 : 2;   // ys==0 row (origin is r2<=4)
    return 1 + ring * 4 + bin;
}

struct SegTab {
    short iy[512];
    short a[512];
    short b[512];
    int   start[14];
    float w[13];
};

__host__ __device__ constexpr SegTab make_segs() {
    SegTab t{};
    int cnt[13] = {};
    for (int iy = 0; iy < 33; iy++)
        for (int ix = 0; ix < 33; ix++)
            cnt[region_of(16 - iy, 16 - ix)]++;
    int pos = 0;
    for (int r = 0; r < 13; r++) {
        t.start[r] = pos;
        t.w[r] = 1.0f / (float)cnt[r];
        for (int iy = 0; iy < 33; iy++) {
            int ix = 0;
            while (ix < 33) {
                if (region_of(16 - iy, 16 - ix) == r) {
                    int a0 = ix;
                    while (ix < 33 && region_of(16 - iy, 16 - ix) == r) ix++;
                    t.iy[pos] = (short)iy;
                    t.a[pos]  = (short)a0;
                    t.b[pos]  = (short)(ix - 1);
                    pos++;
                } else ix++;
            }
        }
    }
    t.start[13] = pos;
    return t;
}

// ---------------- Kernel A: fused 1x1 convs, ONE batch image -------------
// TLB-safe geometry (R9/R10-proven): 148 blocks, contiguous pixel groups,
// per-block page footprint ~70 (channel-dim dominated). 222 active threads.
#define FMA2(d, a, b) asm("fma.rn.f32x2 %0, %1, %2, %0;" : "+l"(d) : "l"(a), "l"(b))
#define CB 8
#define NGRP_H  32768        // 4-px groups per batch image = HW/4
#define GPB_H   222          // ceil(NGRP_H / 148)

__global__ void __launch_bounds__(256, 1) k_head(
    const float* __restrict__ x, int b,
    const float* __restrict__ pos_w, const float* __restrict__ pos_b,
    const float* __restrict__ reg_w, const float* __restrict__ reg_b,
    const float* __restrict__ off_w, const float* __restrict__ off_b,
    float* __restrict__ out)
{
    __shared__ __align__(16) ull wdup[NC * NOUT];

    const int tid = threadIdx.x;
    for (int i = tid; i < NC * NOUT; i += 256) {
        int c = i >> 4, o = i & 15;
        float w = (o < 13) ? pos_w[o * NC + c]
                : (o == 13) ? reg_w[c]
                : off_w[(o - 14) * NC + c];
        unsigned int u = __float_as_uint(w);
        wdup[i] = (ull)u | ((ull)u << 32);
    }
    __syncthreads();

    const int g = blockIdx.x * GPB_H + tid;        // 4-px group id within batch b
    if (tid >= GPB_H || g >= NGRP_H) return;       // after the only barrier
    const int p0 = g * 4;
    const float* xp = x + (size_t)b * NC * HW + p0;

    ull acc[2][NOUT];
    #pragma unroll
    for (int gi = 0; gi < 2; gi++)
        #pragma unroll
        for (int o = 0; o < NOUT; o++) acc[gi][o] = 0ull;

    #pragma unroll 1
    for (int cb = 0; cb < NC; cb += CB) {
        // front-batched independent loads (MLP = CB)
        ulonglong2 xv[CB];
        #pragma unroll
        for (int j = 0; j < CB; j++)
            xv[j] = *reinterpret_cast<const ulonglong2*>(xp + (size_t)(cb + j) * HW);

        #pragma unroll
        for (int j = 0; j < CB; j++) {
            const ulonglong2* wp =
                reinterpret_cast<const ulonglong2*>(wdup + (cb + j) * NOUT);
            #pragma unroll
            for (int k = 0; k < 8; k++) {
                ulonglong2 wv = wp[k];   // {w(2k),w(2k)}, {w(2k+1),w(2k+1)}
                FMA2(acc[0][2 * k],     xv[j].x, wv.x);
                FMA2(acc[1][2 * k],     xv[j].y, wv.x);
                FMA2(acc[0][2 * k + 1], xv[j].x, wv.y);
                FMA2(acc[1][2 * k + 1], xv[j].y, wv.y);
            }
        }
    }

    // Epilogue: bias, relu for evident, route to scratch / out
    #pragma unroll
    for (int o = 0; o < NOUT; o++) {
        float bias = (o < 13) ? pos_b[o] : (o == 13) ? reg_b[0] : off_b[o - 14];
        float4 v;
        v.x = __uint_as_float((unsigned)(acc[0][o]))       + bias;
        v.y = __uint_as_float((unsigned)(acc[0][o] >> 32)) + bias;
        v.z = __uint_as_float((unsigned)(acc[1][o]))       + bias;
        v.w = __uint_as_float((unsigned)(acc[1][o] >> 32)) + bias;
        if (o < 13) {
            v.x = fmaxf(v.x, 0.f); v.y = fmaxf(v.y, 0.f);
            v.z = fmaxf(v.z, 0.f); v.w = fmaxf(v.w, 0.f);
            float* dst = g_ev + (size_t)(b * 13 + o) * HW;
            *reinterpret_cast<float4*>(dst + p0) = v;
        } else if (o == 13) {
            float* dst = out + 2 * HW + (size_t)b * HW;   // x_reg block
            *reinterpret_cast<float4*>(dst + p0) = v;
        } else {
            float* dst = out + 4 * HW + (size_t)(b * 2 + (o - 14)) * HW; // x_off
            *reinterpret_cast<float4*>(dst + p0) = v;
        }
    }
}

// ---------------- Kernel B: Hough vote conv + sigmoid, ONE batch ---------
// (logic identical to the 31.1us-stable version; batch as parameter)
#define PSTR 65

template<int R>
__device__ __forceinline__ float gather_region(const float* __restrict__ buf, int pbase) {
    constexpr SegTab t = make_segs();
    constexpr int j0 = t.start[R];
    constexpr int j1 = t.start[R + 1];
    float s0 = 0.f, s1 = 0.f, s2 = 0.f, s3 = 0.f;
    #pragma unroll
    for (int j = j0; j < j1; j++) {
        int ro = t.iy[j] * PSTR;
        float d = buf[pbase + ro + t.b[j] + 1] - buf[pbase + ro + t.a[j]];
        int lane4 = j & 3;
        if      (lane4 == 0) s0 += d;
        else if (lane4 == 1) s1 += d;
        else if (lane4 == 2) s2 += d;
        else                 s3 += d;
    }
    return ((s0 + s1) + (s2 + s3)) * t.w[R];
}

template<int R> struct ChanLoop {
    static __device__ __forceinline__ float run(
        int b, int y0, int x0, int lane, int wrp, int pbase,
        float* __restrict__ sP0, float* __restrict__ sP1)
    {
        float* buf = (R & 1) ? sP1 : sP0;
        const float* ev = g_ev + (size_t)(b * 13 + R) * HW;

        #pragma unroll
        for (int k = 0; k < 2; k++) {
            int row = 2 * wrp + k;
            int gy  = y0 + row - 16;
            int gx  = x0 + 2 * lane - 16;
            float v0 = 0.f, v1 = 0.f;
            if ((unsigned)gy < (unsigned)H_IMG) {
                const float* rp = ev + gy * W_IMG;
                if ((unsigned)gx       < (unsigned)W_IMG) v0 = rp[gx];
                if ((unsigned)(gx + 1) < (unsigned)W_IMG) v1 = rp[gx + 1];
            }
            float s = v0 + v1;
            float inc = s;
            #pragma unroll
            for (int d = 1; d < 32; d <<= 1) {
                float n = __shfl_up_sync(0xffffffffu, inc, d);
                if (lane >= d) inc += n;
            }
            float excl = inc - s;
            float* rowp = buf + row * PSTR;   // rowp[j] = sum of cols [0, j)
            if (lane == 0) rowp[0] = 0.f;
            rowp[2 * lane + 1] = excl + v0;
            rowp[2 * lane + 2] = inc;
        }
        __syncthreads();
        float part = gather_region<R>(buf, pbase);
        return part + ChanLoop<R + 1>::run(b, y0, x0, lane, wrp, pbase, sP0, sP1);
    }
};

template<> struct ChanLoop<13> {
    static __device__ __forceinline__ float run(int, int, int, int, int, int, float*, float*) {
        return 0.f;
    }
};

__global__ void __launch_bounds__(1024) k_hough(float* __restrict__ out, int b)
{
    __shared__ float sP[2][64 * PSTR];

    const int tid  = threadIdx.x;
    const int lane = tid & 31;
    const int wrp  = tid >> 5;
    const int y0 = blockIdx.y * 32;
    const int x0 = blockIdx.x * 32;
    const int pbase = wrp * PSTR + lane;

    float score = ChanLoop<0>::run(b, y0, x0, lane, wrp, pbase, sP[0], sP[1]);

    out[(size_t)b * HW + (y0 + wrp) * W_IMG + (x0 + lane)] =
        1.f / (1.f + __expf(-score));
}

// ---------------- launch: batch-split with cross-stream overlap ----------
// hough(b=0) runs on an auxiliary non-blocking stream concurrently with
// head(b=1): they saturate different pipes (MIO/LDS vs FMA issue).
// Fork/join via events — the documented graph-capture pattern.
extern "C" void kernel_launch(void* const* d_in, const int* in_sizes, int n_in,
                              void* d_out, int out_size)
{
    const float* x     = (const float*)d_in[0];
    const float* pos_w = (const float*)d_in[1];
    const float* pos_b = (const float*)d_in[2];
    const float* reg_w = (const float*)d_in[3];
    const float* reg_b = (const float*)d_in[4];
    const float* off_w = (const float*)d_in[5];
    const float* off_b = (const float*)d_in[6];
    float* out = (float*)d_out;

    static cudaStream_t s_aux = nullptr;
    static cudaEvent_t ev_fork = nullptr, ev_join = nullptr;
    if (s_aux == nullptr) {
        cudaStreamCreateWithFlags(&s_aux, cudaStreamNonBlocking);
        cudaEventCreateWithFlags(&ev_fork, cudaEventDisableTiming);
        cudaEventCreateWithFlags(&ev_join, cudaEventDisableTiming);
    }

    dim3 gB(W_IMG / 32, H_IMG / 32);

    // head(b=0) on main stream
    k_head<<<148, 256>>>(x, 0, pos_w, pos_b, reg_w, reg_b, off_w, off_b, out);
    cudaEventRecord(ev_fork, 0);

    // aux branch: hough(b=0) — overlaps with head(b=1) below
    cudaStreamWaitEvent(s_aux, ev_fork, 0);
    k_hough<<<gB, 1024, 0, s_aux>>>(out, 0);
    cudaEventRecord(ev_join, s_aux);

    // main stream continues: head(b=1), then hough(b=1)
    k_head<<<148, 256>>>(x, 1, pos_w, pos_b, reg_w, reg_b, off_w, off_b, out);
    k_hough<<<gB, 1024>>>(out, 1);

    // join aux branch before graph end
    cudaStreamWaitEvent(0, ev_join, 0);
}

// round 13
// speedup vs baseline: 1.4943x; 1.4943x over previous
#include <cuda_runtime.h>
#include <math.h>

#define HW      131072      // 256*512
#define W_IMG   512
#define H_IMG   256
#define NC      256
#define NB      2
#define NOUT    16          // 13 pos + 1 reg + 2 off

typedef unsigned long long ull;

// Scratch for evident = relu(pos conv): [2,13,H,W]
__device__ float g_ev[NB * 13 * HW];

// ---------------- compile-time Hough region geometry ----------------
__host__ __device__ constexpr int region_of(int ys, int xs) {
    int r2 = ys * ys + xs * xs;
    if (r2 <= 4) return 0;
    int ring = (r2 <= 64) ? 0 : (r2 <= 256) ? 1 : 2;
    int bin = 0;
    if (ys > 0)      bin = (xs > 0) ? 0 : 1;
    else if (ys < 0) bin = (xs < 0) ? 2 : 3;
    else             bin = (xs > 0) ? 0 : 2;   // ys==0 row (origin is r2<=4)
    return 1 + ring * 4 + bin;
}

struct SegTab {
    short iy[512];
    short a[512];
    short b[512];
    int   start[14];
    float w[13];
};

__host__ __device__ constexpr SegTab make_segs() {
    SegTab t{};
    int cnt[13] = {};
    for (int iy = 0; iy < 33; iy++)
        for (int ix = 0; ix < 33; ix++)
            cnt[region_of(16 - iy, 16 - ix)]++;
    int pos = 0;
    for (int r = 0; r < 13; r++) {
        t.start[r] = pos;
        t.w[r] = 1.0f / (float)cnt[r];
        for (int iy = 0; iy < 33; iy++) {
            int ix = 0;
            while (ix < 33) {
                if (region_of(16 - iy, 16 - ix) == r) {
                    int a0 = ix;
                    while (ix < 33 && region_of(16 - iy, 16 - ix) == r) ix++;
                    t.iy[pos] = (short)iy;
                    t.a[pos]  = (short)a0;
                    t.b[pos]  = (short)(ix - 1);
                    pos++;
                } else ix++;
            }
        }
    }
    t.start[13] = pos;
    return t;
}

// ---------------- Kernel A: fused 1x1 convs (R10-proven, 67.3us) ----------
// TLB-safe geometry: 148 blocks (1/SM, single wave), 443 active threads of
// 512, 4 px/thread, CB=8 front-batched LDG.128, weights as {w,w} in shared.
#define FMA2(d, a, b) asm("fma.rn.f32x2 %0, %1, %2, %0;" : "+l"(d) : "l"(a), "l"(b))
#define CB 8
#define NGRP  65536          // total 4-px groups = NB*HW/4
#define GPB   443            // ceil(NGRP / 148)

__global__ void __launch_bounds__(512, 1) k_head(
    const float* __restrict__ x,
    const float* __restrict__ pos_w, const float* __restrict__ pos_b,
    const float* __restrict__ reg_w, const float* __restrict__ reg_b,
    const float* __restrict__ off_w, const float* __restrict__ off_b,
    float* __restrict__ out)
{
    __shared__ __align__(16) ull wdup[NC * NOUT];

    const int tid = threadIdx.x;
    for (int i = tid; i < NC * NOUT; i += 512) {
        int c = i >> 4, o = i & 15;
        float w = (o < 13) ? pos_w[o * NC + c]
                : (o == 13) ? reg_w[c]
                : off_w[(o - 14) * NC + c];
        unsigned int u = __float_as_uint(w);
        wdup[i] = (ull)u | ((ull)u << 32);
    }
    __syncthreads();

    const int g = blockIdx.x * GPB + tid;          // 4-px group id
    if (tid >= GPB || g >= NGRP) return;           // after the only barrier
    const int b  = g >> 15;                        // g / (HW/4)
    const int p0 = (g & 32767) * 4;
    const float* xp = x + (size_t)b * NC * HW + p0;

    ull acc[2][NOUT];
    #pragma unroll
    for (int gi = 0; gi < 2; gi++)
        #pragma unroll
        for (int o = 0; o < NOUT; o++) acc[gi][o] = 0ull;

    #pragma unroll 1
    for (int cb = 0; cb < NC; cb += CB) {
        // front-batched independent loads (MLP = CB)
        ulonglong2 xv[CB];
        #pragma unroll
        for (int j = 0; j < CB; j++)
            xv[j] = *reinterpret_cast<const ulonglong2*>(xp + (size_t)(cb + j) * HW);

        #pragma unroll
        for (int j = 0; j < CB; j++) {
            const ulonglong2* wp =
                reinterpret_cast<const ulonglong2*>(wdup + (cb + j) * NOUT);
            #pragma unroll
            for (int k = 0; k < 8; k++) {
                ulonglong2 wv = wp[k];   // {w(2k),w(2k)}, {w(2k+1),w(2k+1)}
                FMA2(acc[0][2 * k],     xv[j].x, wv.x);
                FMA2(acc[1][2 * k],     xv[j].y, wv.x);
                FMA2(acc[0][2 * k + 1], xv[j].x, wv.y);
                FMA2(acc[1][2 * k + 1], xv[j].y, wv.y);
            }
        }
    }

    // Epilogue: bias, relu for evident, route to scratch / out
    #pragma unroll
    for (int o = 0; o < NOUT; o++) {
        float bias = (o < 13) ? pos_b[o] : (o == 13) ? reg_b[0] : off_b[o - 14];
        float4 v;
        v.x = __uint_as_float((unsigned)(acc[0][o]))       + bias;
        v.y = __uint_as_float((unsigned)(acc[0][o] >> 32)) + bias;
        v.z = __uint_as_float((unsigned)(acc[1][o]))       + bias;
        v.w = __uint_as_float((unsigned)(acc[1][o] >> 32)) + bias;
        if (o < 13) {
            v.x = fmaxf(v.x, 0.f); v.y = fmaxf(v.y, 0.f);
            v.z = fmaxf(v.z, 0.f); v.w = fmaxf(v.w, 0.f);
            float* dst = g_ev + (size_t)(b * 13 + o) * HW;
            *reinterpret_cast<float4*>(dst + p0) = v;
        } else if (o == 13) {
            float* dst = out + 2 * HW + (size_t)b * HW;   // x_reg block
            *reinterpret_cast<float4*>(dst + p0) = v;
        } else {
            float* dst = out + 4 * HW + (size_t)(b * 2 + (o - 14)) * HW; // x_off
            *reinterpret_cast<float4*>(dst + p0) = v;
        }
    }
}

// ---------------- Kernel B: Hough vote conv + sigmoid ----------------
// Pairwise channel processing with 4 shared buffers: scan+store channels
// 2P,2P+1 into two fresh buffers, ONE barrier, gather both. Barriers 13 -> 7;
// load MLP and gather ILP doubled. Buffer reuse safe by double-buffer rotation.
#define PSTR 65
#define HBUF (64 * PSTR)
#define SMEM_HOUGH (4 * HBUF * (int)sizeof(float))   // 66560 B (dynamic)

template<int R>
__device__ __forceinline__ void scan_store(
    int b, int y0, int x0, int lane, int wrp, float* __restrict__ buf)
{
    const float* ev = g_ev + (size_t)(b * 13 + R) * HW;
    #pragma unroll
    for (int k = 0; k < 2; k++) {
        int row = 2 * wrp + k;
        int gy  = y0 + row - 16;
        int gx  = x0 + 2 * lane - 16;
        float v0 = 0.f, v1 = 0.f;
        if ((unsigned)gy < (unsigned)H_IMG) {
            const float* rp = ev + gy * W_IMG;
            if ((unsigned)gx       < (unsigned)W_IMG) v0 = rp[gx];
            if ((unsigned)(gx + 1) < (unsigned)W_IMG) v1 = rp[gx + 1];
        }
        float s = v0 + v1;
        float inc = s;
        #pragma unroll
        for (int d = 1; d < 32; d <<= 1) {
            float n = __shfl_up_sync(0xffffffffu, inc, d);
            if (lane >= d) inc += n;
        }
        float excl = inc - s;
        float* rowp = buf + row * PSTR;   // rowp[j] = sum of cols [0, j)
        if (lane == 0) rowp[0] = 0.f;
        rowp[2 * lane + 1] = excl + v0;
        rowp[2 * lane + 2] = inc;
    }
}

template<int R>
__device__ __forceinline__ float gather_region(const float* __restrict__ buf, int pbase) {
    constexpr SegTab t = make_segs();
    constexpr int j0 = t.start[R];
    constexpr int j1 = t.start[R + 1];
    float s0 = 0.f, s1 = 0.f, s2 = 0.f, s3 = 0.f;
    #pragma unroll
    for (int j = j0; j < j1; j++) {
        int ro = t.iy[j] * PSTR;
        float d = buf[pbase + ro + t.b[j] + 1] - buf[pbase + ro + t.a[j]];
        int lane4 = j & 3;
        if      (lane4 == 0) s0 += d;
        else if (lane4 == 1) s1 += d;
        else if (lane4 == 2) s2 += d;
        else                 s3 += d;
    }
    return ((s0 + s1) + (s2 + s3)) * t.w[R];
}

template<int P> struct PairLoop {
    static __device__ __forceinline__ float run(
        int b, int y0, int x0, int lane, int wrp, int pbase,
        float* s0, float* s1, float* s2, float* s3)
    {
        float* bA = (P & 1) ? s2 : s0;
        float* bB = (P & 1) ? s3 : s1;
        scan_store<2 * P>    (b, y0, x0, lane, wrp, bA);
        scan_store<2 * P + 1>(b, y0, x0, lane, wrp, bB);
        __syncthreads();
        float part = gather_region<2 * P>(bA, pbase)
                   + gather_region<2 * P + 1>(bB, pbase);
        return part + PairLoop<P + 1>::run(b, y0, x0, lane, wrp, pbase, s0, s1, s2, s3);
    }
};

template<> struct PairLoop<6> {
    static __device__ __forceinline__ float run(
        int b, int y0, int x0, int lane, int wrp, int pbase,
        float* s0, float* s1, float* s2, float* s3)
    {
        // channel 12 alone; s0's last readers (pair 4) finished before pair 5's
        // barrier, so overwriting s0 here is safe.
        scan_store<12>(b, y0, x0, lane, wrp, s0);
        __syncthreads();
        return gather_region<12>(s0, pbase);
    }
};

__global__ void __launch_bounds__(1024) k_hough(float* __restrict__ out)
{
    extern __shared__ float sbuf[];
    float* s0 = sbuf;
    float* s1 = sbuf + HBUF;
    float* s2 = sbuf + 2 * HBUF;
    float* s3 = sbuf + 3 * HBUF;

    const int tid  = threadIdx.x;
    const int lane = tid & 31;
    const int wrp  = tid >> 5;
    const int b  = blockIdx.z;
    const int y0 = blockIdx.y * 32;
    const int x0 = blockIdx.x * 32;
    const int pbase = wrp * PSTR + lane;

    float score = PairLoop<0>::run(b, y0, x0, lane, wrp, pbase, s0, s1, s2, s3);

    out[(size_t)b * HW + (y0 + wrp) * W_IMG + (x0 + lane)] =
        1.f / (1.f + __expf(-score));
}

// ---------------- launch (single stream, R10 structure) ----------------
extern "C" void kernel_launch(void* const* d_in, const int* in_sizes, int n_in,
                              void* d_out, int out_size)
{
    const float* x     = (const float*)d_in[0];
    const float* pos_w = (const float*)d_in[1];
    const float* pos_b = (const float*)d_in[2];
    const float* reg_w = (const float*)d_in[3];
    const float* reg_b = (const float*)d_in[4];
    const float* off_w = (const float*)d_in[5];
    const float* off_b = (const float*)d_in[6];
    float* out = (float*)d_out;

    cudaFuncSetAttribute(k_hough, cudaFuncAttributeMaxDynamicSharedMemorySize,
                         SMEM_HOUGH);

    k_head<<<148, 512>>>(x, pos_w, pos_b, reg_w, reg_b, off_w, off_b, out);

    dim3 gB(W_IMG / 32, H_IMG / 32, NB);
    k_hough<<<gB, 1024, SMEM_HOUGH>>>(out);
}

// round 14
// speedup vs baseline: 1.5761x; 1.0548x over previous
#include <cuda_runtime.h>
#include <math.h>

#define HW      131072      // 256*512
#define W_IMG   512
#define H_IMG   256
#define NC      256
#define NB      2
#define NOUT    16          // 13 pos + 1 reg + 2 off

typedef unsigned long long ull;

// Scratch for evident = relu(pos conv): [2,13,H,W]
__device__ float g_ev[NB * 13 * HW];

// ---------------- compile-time Hough region geometry ----------------
__host__ __device__ constexpr int region_of(int ys, int xs) {
    int r2 = ys * ys + xs * xs;
    if (r2 <= 4) return 0;
    int ring = (r2 <= 64) ? 0 : (r2 <= 256) ? 1 : 2;
    int bin = 0;
    if (ys > 0)      bin = (xs > 0) ? 0 : 1;
    else if (ys < 0) bin = (xs < 0) ? 2 : 3;
    else             bin = (xs > 0) ? 0 : 2;   // ys==0 row (origin is r2<=4)
    return 1 + ring * 4 + bin;
}

struct SegTab {
    short iy[512];
    short a[512];
    short b[512];
    int   start[14];
    float w[13];
};

__host__ __device__ constexpr SegTab make_segs() {
    SegTab t{};
    int cnt[13] = {};
    for (int iy = 0; iy < 33; iy++)
        for (int ix = 0; ix < 33; ix++)
            cnt[region_of(16 - iy, 16 - ix)]++;
    int pos = 0;
    for (int r = 0; r < 13; r++) {
        t.start[r] = pos;
        t.w[r] = 1.0f / (float)cnt[r];
        for (int iy = 0; iy < 33; iy++) {
            int ix = 0;
            while (ix < 33) {
                if (region_of(16 - iy, 16 - ix) == r) {
                    int a0 = ix;
                    while (ix < 33 && region_of(16 - iy, 16 - ix) == r) ix++;
                    t.iy[pos] = (short)iy;
                    t.a[pos]  = (short)a0;
                    t.b[pos]  = (short)(ix - 1);
                    pos++;
                } else ix++;
            }
        }
    }
    t.start[13] = pos;
    return t;
}

// ---------------- Kernel A: fused 1x1 convs (R10-proven, 66.2us) ----------
// TLB-safe geometry: 148 blocks (1/SM, single wave), 443 active threads of
// 512, 4 px/thread, CB=8 front-batched LDG.128, weights as {w,w} in shared.
#define FMA2(d, a, b) asm("fma.rn.f32x2 %0, %1, %2, %0;" : "+l"(d) : "l"(a), "l"(b))
#define CB 8
#define NGRP  65536          // total 4-px groups = NB*HW/4
#define GPB   443            // ceil(NGRP / 148)

__global__ void __launch_bounds__(512, 1) k_head(
    const float* __restrict__ x,
    const float* __restrict__ pos_w, const float* __restrict__ pos_b,
    const float* __restrict__ reg_w, const float* __restrict__ reg_b,
    const float* __restrict__ off_w, const float* __restrict__ off_b,
    float* __restrict__ out)
{
    __shared__ __align__(16) ull wdup[NC * NOUT];

    const int tid = threadIdx.x;
    for (int i = tid; i < NC * NOUT; i += 512) {
        int c = i >> 4, o = i & 15;
        float w = (o < 13) ? pos_w[o * NC + c]
                : (o == 13) ? reg_w[c]
                : off_w[(o - 14) * NC + c];
        unsigned int u = __float_as_uint(w);
        wdup[i] = (ull)u | ((ull)u << 32);
    }
    __syncthreads();

    const int g = blockIdx.x * GPB + tid;          // 4-px group id
    if (tid >= GPB || g >= NGRP) return;           // after the only barrier
    const int b  = g >> 15;                        // g / (HW/4)
    const int p0 = (g & 32767) * 4;
    const float* xp = x + (size_t)b * NC * HW + p0;

    ull acc[2][NOUT];
    #pragma unroll
    for (int gi = 0; gi < 2; gi++)
        #pragma unroll
        for (int o = 0; o < NOUT; o++) acc[gi][o] = 0ull;

    #pragma unroll 1
    for (int cb = 0; cb < NC; cb += CB) {
        // front-batched independent loads (MLP = CB)
        ulonglong2 xv[CB];
        #pragma unroll
        for (int j = 0; j < CB; j++)
            xv[j] = *reinterpret_cast<const ulonglong2*>(xp + (size_t)(cb + j) * HW);

        #pragma unroll
        for (int j = 0; j < CB; j++) {
            const ulonglong2* wp =
                reinterpret_cast<const ulonglong2*>(wdup + (cb + j) * NOUT);
            #pragma unroll
            for (int k = 0; k < 8; k++) {
                ulonglong2 wv = wp[k];   // {w(2k),w(2k)}, {w(2k+1),w(2k+1)}
                FMA2(acc[0][2 * k],     xv[j].x, wv.x);
                FMA2(acc[1][2 * k],     xv[j].y, wv.x);
                FMA2(acc[0][2 * k + 1], xv[j].x, wv.y);
                FMA2(acc[1][2 * k + 1], xv[j].y, wv.y);
            }
        }
    }

    // Epilogue: bias, relu for evident, route to scratch / out
    #pragma unroll
    for (int o = 0; o < NOUT; o++) {
        float bias = (o < 13) ? pos_b[o] : (o == 13) ? reg_b[0] : off_b[o - 14];
        float4 v;
        v.x = __uint_as_float((unsigned)(acc[0][o]))       + bias;
        v.y = __uint_as_float((unsigned)(acc[0][o] >> 32)) + bias;
        v.z = __uint_as_float((unsigned)(acc[1][o]))       + bias;
        v.w = __uint_as_float((unsigned)(acc[1][o] >> 32)) + bias;
        if (o < 13) {
            v.x = fmaxf(v.x, 0.f); v.y = fmaxf(v.y, 0.f);
            v.z = fmaxf(v.z, 0.f); v.w = fmaxf(v.w, 0.f);
            float* dst = g_ev + (size_t)(b * 13 + o) * HW;
            *reinterpret_cast<float4*>(dst + p0) = v;
        } else if (o == 13) {
            float* dst = out + 2 * HW + (size_t)b * HW;   // x_reg block
            *reinterpret_cast<float4*>(dst + p0) = v;
        } else {
            float* dst = out + 4 * HW + (size_t)(b * 2 + (o - 14)) * HW; // x_off
            *reinterpret_cast<float4*>(dst + p0) = v;
        }
    }
}

// ---------------- Kernel B: Hough vote conv + sigmoid ----------------
// 32x32 tile, 13 channels, 2 rotating prefix buffers. NEW: vectorized scan —
// one LDG.128 per warp covers both halo rows (float4/lane, 16-lane segments),
// width-16 segmented shfl scan (4 shfl), one aligned STS.128 per lane for the
// exclusive prefix (PSTR=68 keeps 16B alignment), +1 scalar STS for P[64].
#define PSTR 68

template<int R>
__device__ __forceinline__ void scan_store(
    int b, int y0, int x0, int lane, int wrp, float* __restrict__ buf)
{
    const float* ev = g_ev + (size_t)(b * 13 + R) * HW;
    const int seg = lane >> 4;         // 0: row 2*wrp, 1: row 2*wrp+1
    const int sl  = lane & 15;
    const int row = 2 * wrp + seg;
    const int gy  = y0 + row - 16;
    const int gx  = x0 + sl * 4 - 16;

    float4 v = make_float4(0.f, 0.f, 0.f, 0.f);
    if ((unsigned)gy < (unsigned)H_IMG && (unsigned)gx <= (unsigned)(W_IMG - 4))
        v = *reinterpret_cast<const float4*>(ev + gy * W_IMG + gx);

    float s  = ((v.x + v.y) + (v.z + v.w));
    float inc = s;
    #pragma unroll
    for (int d = 1; d < 16; d <<= 1) {
        float n = __shfl_up_sync(0xffffffffu, inc, d, 16);
        if (sl >= d) inc += n;
    }
    float excl = inc - s;

    float* rowp = buf + row * PSTR;    // P[c] = sum of cols [0, c)
    float4 pq;
    pq.x = excl;
    pq.y = excl + v.x;
    pq.z = pq.y + v.y;
    pq.w = pq.z + v.z;
    *reinterpret_cast<float4*>(rowp + 4 * sl) = pq;   // P[4sl .. 4sl+3], 16B-aligned
    if (sl == 15) rowp[64] = inc;                      // P[64] = row total
}

template<int R>
__device__ __forceinline__ float gather_region(const float* __restrict__ buf, int pbase) {
    constexpr SegTab t = make_segs();
    constexpr int j0 = t.start[R];
    constexpr int j1 = t.start[R + 1];
    float s0 = 0.f, s1 = 0.f, s2 = 0.f, s3 = 0.f;
    #pragma unroll
    for (int j = j0; j < j1; j++) {
        int ro = t.iy[j] * PSTR;
        float d = buf[pbase + ro + t.b[j] + 1] - buf[pbase + ro + t.a[j]];
        int lane4 = j & 3;
        if      (lane4 == 0) s0 += d;
        else if (lane4 == 1) s1 += d;
        else if (lane4 == 2) s2 += d;
        else                 s3 += d;
    }
    return ((s0 + s1) + (s2 + s3)) * t.w[R];
}

template<int R> struct ChanLoop {
    static __device__ __forceinline__ float run(
        int b, int y0, int x0, int lane, int wrp, int pbase,
        float* __restrict__ sP0, float* __restrict__ sP1)
    {
        float* buf = (R & 1) ? sP1 : sP0;
        scan_store<R>(b, y0, x0, lane, wrp, buf);
        __syncthreads();
        float part = gather_region<R>(buf, pbase);
        return part + ChanLoop<R + 1>::run(b, y0, x0, lane, wrp, pbase, sP0, sP1);
    }
};

template<> struct ChanLoop<13> {
    static __device__ __forceinline__ float run(int, int, int, int, int, int, float*, float*) {
        return 0.f;
    }
};

__global__ void __launch_bounds__(1024) k_hough(float* __restrict__ out)
{
    __shared__ __align__(16) float sP[2][64 * PSTR];

    const int tid  = threadIdx.x;
    const int lane = tid & 31;
    const int wrp  = tid >> 5;
    const int b  = blockIdx.z;
    const int y0 = blockIdx.y * 32;
    const int x0 = blockIdx.x * 32;
    const int pbase = wrp * PSTR + lane;

    float score = ChanLoop<0>::run(b, y0, x0, lane, wrp, pbase, sP[0], sP[1]);

    out[(size_t)b * HW + (y0 + wrp) * W_IMG + (x0 + lane)] =
        1.f / (1.f + __expf(-score));
}

// ---------------- launch ----------------
extern "C" void kernel_launch(void* const* d_in, const int* in_sizes, int n_in,
                              void* d_out, int out_size)
{
    const float* x     = (const float*)d_in[0];
    const float* pos_w = (const float*)d_in[1];
    const float* pos_b = (const float*)d_in[2];
    const float* reg_w = (const float*)d_in[3];
    const float* reg_b = (const float*)d_in[4];
    const float* off_w = (const float*)d_in[5];
    const float* off_b = (const float*)d_in[6];
    float* out = (float*)d_out;

    k_head<<<148, 512>>>(x, pos_w, pos_b, reg_w, reg_b, off_w, off_b, out);

    dim3 gB(W_IMG / 32, H_IMG / 32, NB);
    k_hough<<<gB, 1024>>>(out);
}